// round 8
// baseline (speedup 1.0000x reference)
#include <cuda_runtime.h>
#include <stdint.h>
#include <math.h>

#define BATCH 4
#define CDIM 128
#define HWDIM 4096
#define NGROUP 8
#define CPG 16
#define NH 4
#define HD 32
#define OC 384   // 3*C

// Scratch (allocation-free: device globals)
__device__ float g_xn[BATCH * CDIM * HWDIM];
__device__ float g_qkv[BATCH * OC * HWDIM];
__device__ float g_att[BATCH * CDIM * HWDIM];
__device__ float g_mean[BATCH * NGROUP];
__device__ float g_rstd[BATCH * NGROUP];

__device__ __forceinline__ void mma8(float* d, const unsigned* a, float b0f, float b1f) {
    unsigned b0 = __float_as_uint(b0f), b1 = __float_as_uint(b1f);
    asm volatile(
        "mma.sync.aligned.m16n8k8.row.col.f32.tf32.tf32.f32 "
        "{%0,%1,%2,%3},{%4,%5,%6,%7},{%8,%9},{%0,%1,%2,%3};\n"
        : "+f"(d[0]), "+f"(d[1]), "+f"(d[2]), "+f"(d[3])
        : "r"(a[0]), "r"(a[1]), "r"(a[2]), "r"(a[3]), "r"(b0), "r"(b1));
}

__device__ __forceinline__ void cpa16(uint32_t dst, const void* src) {
    asm volatile("cp.async.cg.shared.global [%0], [%1], 16;" :: "r"(dst), "l"(src));
}

// ---------------------------------------------------------------------------
// 1. GroupNorm statistics
// ---------------------------------------------------------------------------
__global__ void gn_stats_kernel(const float* __restrict__ x) {
    int bg = blockIdx.x;
    const float4* p = reinterpret_cast<const float4*>(x + (size_t)bg * CPG * HWDIM);
    const int n4 = CPG * HWDIM / 4;
    float s = 0.f, ss = 0.f;
    for (int i = threadIdx.x; i < n4; i += blockDim.x) {
        float4 v = p[i];
        s  += v.x + v.y + v.z + v.w;
        ss += v.x * v.x + v.y * v.y + v.z * v.z + v.w * v.w;
    }
    __shared__ float sh_s[256], sh_ss[256];
    sh_s[threadIdx.x] = s;
    sh_ss[threadIdx.x] = ss;
    __syncthreads();
    for (int off = 128; off > 0; off >>= 1) {
        if (threadIdx.x < off) {
            sh_s[threadIdx.x]  += sh_s[threadIdx.x + off];
            sh_ss[threadIdx.x] += sh_ss[threadIdx.x + off];
        }
        __syncthreads();
    }
    if (threadIdx.x == 0) {
        const float inv = 1.0f / (float)(CPG * HWDIM);
        float mean = sh_s[0] * inv;
        float var  = sh_ss[0] * inv - mean * mean;
        g_mean[bg] = mean;
        g_rstd[bg] = rsqrtf(var + 1e-5f);
    }
}

// ---------------------------------------------------------------------------
// 2. Apply GroupNorm
// ---------------------------------------------------------------------------
__global__ void gn_apply_kernel(const float* __restrict__ x,
                                const float* __restrict__ w,
                                const float* __restrict__ bias) {
    int i4 = blockIdx.x * blockDim.x + threadIdx.x;
    const int total4 = BATCH * CDIM * HWDIM / 4;
    if (i4 >= total4) return;
    int e  = i4 * 4;
    int c  = (e / HWDIM) % CDIM;
    int bg = e / (CPG * HWDIM);
    float mean = g_mean[bg], rstd = g_rstd[bg];
    float sw = w[c] * rstd;
    float sb = bias[c] - mean * sw;
    float4 v = reinterpret_cast<const float4*>(x)[i4];
    float4 o;
    o.x = v.x * sw + sb;
    o.y = v.y * sw + sb;
    o.z = v.z * sw + sb;
    o.w = v.w * sw + sb;
    reinterpret_cast<float4*>(g_xn)[i4] = o;
}

// ---------------------------------------------------------------------------
// 3/5. Batched GEMM (fp32 SIMT)
// ---------------------------------------------------------------------------
template <int OTOT, bool RESID>
__global__ void __launch_bounds__(256) gemm_kernel(const float* __restrict__ W,
                                                   const float* __restrict__ bias,
                                                   const float* __restrict__ X,
                                                   float* __restrict__ Out,
                                                   const float* __restrict__ resid) {
    int b = blockIdx.z;
    const float* Xb = X + (size_t)b * CDIM * HWDIM;
    float* Ob = Out + (size_t)b * OTOT * HWDIM;
    int o0 = blockIdx.y * 64;
    int t0 = blockIdx.x * 64;
    __shared__ float As[16][64];
    __shared__ float Bs[16][68];
    float acc[4][4];
#pragma unroll
    for (int i = 0; i < 4; i++)
#pragma unroll
        for (int j = 0; j < 4; j++) acc[i][j] = 0.f;

    int tid = threadIdx.x;
    int tx = tid & 15, ty = tid >> 4;

    for (int k0 = 0; k0 < CDIM; k0 += 16) {
#pragma unroll 4
        for (int i = tid; i < 64 * 16; i += 256) {
            int o = i >> 4, k = i & 15;
            As[k][o] = W[(size_t)(o0 + o) * CDIM + k0 + k];
        }
#pragma unroll 4
        for (int i = tid; i < 16 * 64; i += 256) {
            int k = i >> 6, t = i & 63;
            Bs[k][t] = Xb[(size_t)(k0 + k) * HWDIM + t0 + t];
        }
        __syncthreads();
#pragma unroll
        for (int k = 0; k < 16; k++) {
            float a[4], bb[4];
#pragma unroll
            for (int i = 0; i < 4; i++) a[i] = As[k][ty * 4 + i];
#pragma unroll
            for (int j = 0; j < 4; j++) bb[j] = Bs[k][tx * 4 + j];
#pragma unroll
            for (int i = 0; i < 4; i++)
#pragma unroll
                for (int j = 0; j < 4; j++) acc[i][j] += a[i] * bb[j];
        }
        __syncthreads();
    }

#pragma unroll
    for (int i = 0; i < 4; i++) {
        int o = o0 + ty * 4 + i;
        float bo = bias[o];
#pragma unroll
        for (int j = 0; j < 4; j++) {
            int t = t0 + tx * 4 + j;
            float v = acc[i][j] + bo;
            if (RESID) v += resid[(size_t)b * CDIM * HWDIM + (size_t)o * HWDIM + t];
            Ob[(size_t)o * HWDIM + t] = v;
        }
    }
}

// ---------------------------------------------------------------------------
// 4. Flash attention, tf32 mma. 256 threads, 8 warps x 16 queries, 64-key tiles.
//    cp.async (16B) stages tile t+1 in natural layout DURING compute of tile t;
//    scatter pass moves it into conflict-free fragment-native kf/vf layouts.
//    No-max exp2 softmax.
//    smem (floats): [0,4608)       q_s[128][36] -> p_s[128][36]
//                   [4608,6656)    kf: 8 nf x 32 lanes x 8 (XOR-swizzled)
//                   [6656,8704)    vf: 4 nf x 32 lanes x 16 (rot-swizzled)
//                   [8704,10880)   stage_k[32ch][68]
//                   [10880,13056)  stage_v[32ch][68]
// ---------------------------------------------------------------------------
#define QS_LD 36
#define AQ_FLOATS (128 * QS_LD)          // 4608
#define KF_FLOATS (8 * 32 * 8)           // 2048
#define VF_FLOATS (4 * 32 * 16)          // 2048
#define STG_LD 68
#define STG_FLOATS (32 * STG_LD)         // 2176
#define ATTN_SMEM_FLOATS (AQ_FLOATS + KF_FLOATS + VF_FLOATS + 2 * STG_FLOATS)  // 13056

__global__ void __launch_bounds__(256, 2) attn_mma_kernel(const float* __restrict__ qkv,
                                                          float* __restrict__ att) {
    extern __shared__ float smem[];
    float (*q_s)[QS_LD] = (float(*)[QS_LD])smem;
    float (*p_s)[QS_LD] = (float(*)[QS_LD])smem;
    float* kf      = smem + AQ_FLOATS;
    float* vf      = smem + AQ_FLOATS + KF_FLOATS;
    float* stage_k = smem + AQ_FLOATS + KF_FLOATS + VF_FLOATS;
    float* stage_v = stage_k + STG_FLOATS;

    uint32_t smem_u32;
    asm("{ .reg .u64 t; cvta.to.shared.u64 t, %1; cvt.u32.u64 %0, t; }"
        : "=r"(smem_u32) : "l"(smem));
    const uint32_t stgk_u32 = smem_u32 + (AQ_FLOATS + KF_FLOATS + VF_FLOATS) * 4;
    const uint32_t stgv_u32 = stgk_u32 + STG_FLOATS * 4;

    const int b = blockIdx.z, h = blockIdx.y;
    const int q0 = blockIdx.x * 128;
    const int tid = threadIdx.x;
    const int warp = tid >> 5, lane = tid & 31;
    const int lr = lane >> 2;   // 0..7
    const int lc = lane & 3;    // 0..3
    const int qbase = warp * 16;

    const float* Qb = qkv + ((size_t)b * OC + h * HD) * HWDIM;
    const float* Kb = Qb + (size_t)CDIM * HWDIM;
    const float* Vb = Qb + (size_t)2 * CDIM * HWDIM;
    const float scale = 0.088388347648318447f * 1.4426950408889634f;  // C^-0.5 * log2(e)

    // staging copy indices: chunk c -> ch = c>>4, 16B at key (c&15)*4
    const int s_ch0 = tid >> 4;          // chunks c = tid and c = 256+tid
    const int s_k40 = (tid & 15) * 4;
    // K-scatter thread indices
    const int k_c0  = tid & 3;
    const int k_w   = (tid >> 2) & 3;
    const int k_lr  = (tid >> 4) & 7;
    const int k_nf0 = (tid >> 7) & 1;
    // V-scatter thread indices
    const int v_lc  = tid & 3;
    const int v_e   = (tid >> 2) & 1;
    const int v_lr  = (tid >> 3) & 7;
    const int v_nf  = (tid >> 6) & 3;

    // ---- stage tile 0 ----
    {
        cpa16(stgk_u32 + (s_ch0 * STG_LD + s_k40) * 4, Kb + (size_t)s_ch0 * HWDIM + s_k40);
        cpa16(stgv_u32 + (s_ch0 * STG_LD + s_k40) * 4, Vb + (size_t)s_ch0 * HWDIM + s_k40);
        int ch1 = s_ch0 + 16;
        cpa16(stgk_u32 + (ch1 * STG_LD + s_k40) * 4, Kb + (size_t)ch1 * HWDIM + s_k40);
        cpa16(stgv_u32 + (ch1 * STG_LD + s_k40) * 4, Vb + (size_t)ch1 * HWDIM + s_k40);
        asm volatile("cp.async.commit_group;" ::: "memory");
    }

    // ---- Q tile [128 q][32 ch], pre-scaled ----
    for (int i = tid; i < 32 * 128; i += 256) {
        int ch = i >> 7, qq = i & 127;
        q_s[qq][ch] = Qb[(size_t)ch * HWDIM + q0 + qq] * scale;
    }
    __syncthreads();

    // Q fragments
    unsigned qa[4][4];
    {
        int r0 = qbase + lr;
#pragma unroll
        for (int kk = 0; kk < 4; kk++) {
            int c0 = kk * 8 + lc;
            qa[kk][0] = __float_as_uint(q_s[r0][c0]);
            qa[kk][1] = __float_as_uint(q_s[r0 + 8][c0]);
            qa[kk][2] = __float_as_uint(q_s[r0][c0 + 4]);
            qa[kk][3] = __float_as_uint(q_s[r0 + 8][c0 + 4]);
        }
    }
    asm volatile("cp.async.wait_group 0;" ::: "memory");
    __syncthreads();  // q_s consumed; staging tile 0 visible

    // ---- scatter tile 0 into kf/vf ----
#pragma unroll
    for (int it = 0; it < 8; it++) {
        int g = it & 1, nf = (it >> 1) * 2 + k_nf0;
        int ch = ((g * 4 + k_w) << 2) + k_c0;
        float v = stage_k[ch * STG_LD + nf * 8 + k_lr];
        kf[(nf * 32 + k_lr * 4 + k_c0) * 8 + ((g ^ (k_lr & 1)) << 2) + k_w] = v;
    }
#pragma unroll
    for (int kq = 0; kq < 8; kq++) {
        int key = kq * 8 + v_e * 4 + v_lc;
        float v = stage_v[(v_nf * 8 + v_lr) * STG_LD + key];
        vf[(v_nf * 32 + v_lr * 4 + v_lc) * 16 +
           (((kq + v_lr * 2 + (v_lc >> 1)) & 7) << 1) + v_e] = v;
    }
    __syncthreads();

    float l_i[2] = {0.f, 0.f};
    float oacc[4][4];
#pragma unroll
    for (int nf = 0; nf < 4; nf++)
#pragma unroll
        for (int c = 0; c < 4; c++) oacc[nf][c] = 0.f;

    const int NTILE = HWDIM / 64;  // 64
    for (int t = 0; t < NTILE; t++) {
        // ---- stage tile t+1 while computing tile t ----
        if (t < NTILE - 1) {
            const int j0n = (t + 1) * 64;
            cpa16(stgk_u32 + (s_ch0 * STG_LD + s_k40) * 4,
                  Kb + (size_t)s_ch0 * HWDIM + j0n + s_k40);
            cpa16(stgv_u32 + (s_ch0 * STG_LD + s_k40) * 4,
                  Vb + (size_t)s_ch0 * HWDIM + j0n + s_k40);
            int ch1 = s_ch0 + 16;
            cpa16(stgk_u32 + (ch1 * STG_LD + s_k40) * 4,
                  Kb + (size_t)ch1 * HWDIM + j0n + s_k40);
            cpa16(stgv_u32 + (ch1 * STG_LD + s_k40) * 4,
                  Vb + (size_t)ch1 * HWDIM + j0n + s_k40);
            asm volatile("cp.async.commit_group;" ::: "memory");
        }

        // ---- S = Q @ K^T : 16q x 64k per warp ----
        float sacc[8][4];
#pragma unroll
        for (int nf = 0; nf < 8; nf++)
#pragma unroll
            for (int c = 0; c < 4; c++) sacc[nf][c] = 0.f;

        const int hh = (lr & 1) << 2;
#pragma unroll
        for (int nf = 0; nf < 8; nf++) {
            const float* base = kf + (nf * 32 + lane) * 8;
            float4 fA = *(const float4*)(base + hh);
            float4 fB = *(const float4*)(base + (4 - hh));
            mma8(sacc[nf], qa[0], fA.x, fA.y);
            mma8(sacc[nf], qa[1], fA.z, fA.w);
            mma8(sacc[nf], qa[2], fB.x, fB.y);
            mma8(sacc[nf], qa[3], fB.z, fB.w);
        }

        // ---- softmax numerator (exp2 domain) ----
#pragma unroll
        for (int ri = 0; ri < 2; ri++) {
            float sum = 0.f;
#pragma unroll
            for (int nf = 0; nf < 8; nf++) {
                float p0 = exp2f(sacc[nf][2 * ri]);
                float p1 = exp2f(sacc[nf][2 * ri + 1]);
                sacc[nf][2 * ri] = p0;
                sacc[nf][2 * ri + 1] = p1;
                sum += p0 + p1;
            }
            sum += __shfl_xor_sync(0xffffffffu, sum, 1);
            sum += __shfl_xor_sync(0xffffffffu, sum, 2);
            l_i[ri] += sum;
        }

        // ---- O += P @ V in two 32-key halves ----
#pragma unroll
        for (int khalf = 0; khalf < 2; khalf++) {
            __syncwarp();
            {
                int r0 = qbase + lr;
#pragma unroll
                for (int nf = 0; nf < 4; nf++) {
                    int nfg = khalf * 4 + nf;
                    int col = nf * 8 + 2 * lc;
                    *(float2*)&p_s[r0][col]     = make_float2(sacc[nfg][0], sacc[nfg][1]);
                    *(float2*)&p_s[r0 + 8][col] = make_float2(sacc[nfg][2], sacc[nfg][3]);
                }
            }
            __syncwarp();
#pragma unroll
            for (int kq = 0; kq < 4; kq++) {
                int kqg = khalf * 4 + kq;
                unsigned pa[4];
                {
                    int r0 = qbase + lr;
                    int c0 = kq * 8 + lc;
                    pa[0] = __float_as_uint(p_s[r0][c0]);
                    pa[1] = __float_as_uint(p_s[r0 + 8][c0]);
                    pa[2] = __float_as_uint(p_s[r0][c0 + 4]);
                    pa[3] = __float_as_uint(p_s[r0 + 8][c0 + 4]);
                }
#pragma unroll
                for (int nf = 0; nf < 4; nf++) {
                    float2 v2 = *(const float2*)(vf + (nf * 32 + lane) * 16 +
                                                 (((kqg + (lane >> 1)) & 7) << 1));
                    mma8(oacc[nf], pa, v2.x, v2.y);
                }
            }
        }

        // ---- rotate staged tile into kf/vf ----
        if (t < NTILE - 1) {
            asm volatile("cp.async.wait_group 0;" ::: "memory");
            __syncthreads();  // compute-t reads of kf/vf done; staging visible
#pragma unroll
            for (int it = 0; it < 8; it++) {
                int g = it & 1, nf = (it >> 1) * 2 + k_nf0;
                int ch = ((g * 4 + k_w) << 2) + k_c0;
                float v = stage_k[ch * STG_LD + nf * 8 + k_lr];
                kf[(nf * 32 + k_lr * 4 + k_c0) * 8 + ((g ^ (k_lr & 1)) << 2) + k_w] = v;
            }
#pragma unroll
            for (int kq = 0; kq < 8; kq++) {
                int key = kq * 8 + v_e * 4 + v_lc;
                float v = stage_v[(v_nf * 8 + v_lr) * STG_LD + key];
                vf[(v_nf * 32 + v_lr * 4 + v_lc) * 16 +
                   (((kq + v_lr * 2 + (v_lc >> 1)) & 7) << 1) + v_e] = v;
            }
            __syncthreads();
        }
    }

    // Epilogue: divide by l, write out (att layout [ch][token])
#pragma unroll
    for (int ri = 0; ri < 2; ri++) {
        float inv = 1.f / l_i[ri];
        int q = q0 + qbase + lr + ri * 8;
#pragma unroll
        for (int nf = 0; nf < 4; nf++) {
#pragma unroll
            for (int c = 0; c < 2; c++) {
                int ch = nf * 8 + 2 * lc + c;
                att[((size_t)b * CDIM + h * HD + ch) * HWDIM + q] =
                    oacc[nf][2 * ri + c] * inv;
            }
        }
    }
}

// ---------------------------------------------------------------------------
// Launch
// ---------------------------------------------------------------------------
extern "C" void kernel_launch(void* const* d_in, const int* in_sizes, int n_in,
                              void* d_out, int out_size) {
    const float* x      = (const float*)d_in[0];
    const float* gn_w   = (const float*)d_in[1];
    const float* gn_b   = (const float*)d_in[2];
    const float* qkv_w  = (const float*)d_in[3];
    const float* qkv_b  = (const float*)d_in[4];
    const float* proj_w = (const float*)d_in[5];
    const float* proj_b = (const float*)d_in[6];
    float* out = (float*)d_out;

    float *xn_p, *qkv_p, *att_p;
    cudaGetSymbolAddress((void**)&xn_p, g_xn);
    cudaGetSymbolAddress((void**)&qkv_p, g_qkv);
    cudaGetSymbolAddress((void**)&att_p, g_att);

    static bool attr_set = false;
    if (!attr_set) {
        cudaFuncSetAttribute(attn_mma_kernel,
                             cudaFuncAttributeMaxDynamicSharedMemorySize,
                             ATTN_SMEM_FLOATS * (int)sizeof(float));
        attr_set = true;
    }

    gn_stats_kernel<<<BATCH * NGROUP, 256>>>(x);
    gn_apply_kernel<<<(BATCH * CDIM * HWDIM / 4 + 255) / 256, 256>>>(x, gn_w, gn_b);
    gemm_kernel<OC, false><<<dim3(HWDIM / 64, OC / 64, BATCH), 256>>>(
        qkv_w, qkv_b, xn_p, qkv_p, nullptr);
    attn_mma_kernel<<<dim3(HWDIM / 128, NH, BATCH), 256,
                      ATTN_SMEM_FLOATS * (int)sizeof(float)>>>(qkv_p, att_p);
    gemm_kernel<CDIM, true><<<dim3(HWDIM / 64, CDIM / 64, BATCH), 256>>>(
        proj_w, proj_b, att_p, out, xn_p);
}

// round 9
// speedup vs baseline: 2.4005x; 2.4005x over previous
#include <cuda_runtime.h>
#include <cuda_fp16.h>
#include <stdint.h>
#include <math.h>

#define BATCH 4
#define CDIM 128
#define HWDIM 4096
#define NGROUP 8
#define CPG 16
#define NH 4
#define HD 32
#define OC 384   // 3*C

// Scratch (allocation-free: device globals)
__device__ float g_xn[BATCH * CDIM * HWDIM];
__device__ float g_qkv[BATCH * OC * HWDIM];
__device__ float g_att[BATCH * CDIM * HWDIM];
__device__ float g_mean[BATCH * NGROUP];
__device__ float g_rstd[BATCH * NGROUP];

__device__ __forceinline__ void mma16(float* d, const uint32_t* a, uint32_t b0, uint32_t b1) {
    asm volatile(
        "mma.sync.aligned.m16n8k16.row.col.f32.f16.f16.f32 "
        "{%0,%1,%2,%3},{%4,%5,%6,%7},{%8,%9},{%0,%1,%2,%3};\n"
        : "+f"(d[0]), "+f"(d[1]), "+f"(d[2]), "+f"(d[3])
        : "r"(a[0]), "r"(a[1]), "r"(a[2]), "r"(a[3]), "r"(b0), "r"(b1));
}

__device__ __forceinline__ void ldm4(uint32_t* r, uint32_t addr) {
    asm volatile("ldmatrix.sync.aligned.m8n8.x4.shared.b16 {%0,%1,%2,%3}, [%4];"
                 : "=r"(r[0]), "=r"(r[1]), "=r"(r[2]), "=r"(r[3]) : "r"(addr));
}

__device__ __forceinline__ uint32_t packh2(float lo, float hi) {
    __half2 h = __floats2half2_rn(lo, hi);
    return *reinterpret_cast<uint32_t*>(&h);
}

__device__ __forceinline__ void cpa16(uint32_t dst, const void* src) {
    asm volatile("cp.async.cg.shared.global [%0], [%1], 16;" :: "r"(dst), "l"(src));
}

__device__ __forceinline__ void st32(uint32_t addr, uint32_t v) {
    asm volatile("st.shared.u32 [%0], %1;" :: "r"(addr), "r"(v));
}

__device__ __forceinline__ void sts128u(uint32_t addr, uint32_t a, uint32_t b,
                                        uint32_t c, uint32_t d) {
    asm volatile("st.shared.v4.u32 [%0], {%1,%2,%3,%4};"
                 :: "r"(addr), "r"(a), "r"(b), "r"(c), "r"(d));
}

// ---------------------------------------------------------------------------
// 1. GroupNorm statistics
// ---------------------------------------------------------------------------
__global__ void gn_stats_kernel(const float* __restrict__ x) {
    int bg = blockIdx.x;
    const float4* p = reinterpret_cast<const float4*>(x + (size_t)bg * CPG * HWDIM);
    const int n4 = CPG * HWDIM / 4;
    float s = 0.f, ss = 0.f;
    for (int i = threadIdx.x; i < n4; i += blockDim.x) {
        float4 v = p[i];
        s  += v.x + v.y + v.z + v.w;
        ss += v.x * v.x + v.y * v.y + v.z * v.z + v.w * v.w;
    }
    __shared__ float sh_s[256], sh_ss[256];
    sh_s[threadIdx.x] = s;
    sh_ss[threadIdx.x] = ss;
    __syncthreads();
    for (int off = 128; off > 0; off >>= 1) {
        if (threadIdx.x < off) {
            sh_s[threadIdx.x]  += sh_s[threadIdx.x + off];
            sh_ss[threadIdx.x] += sh_ss[threadIdx.x + off];
        }
        __syncthreads();
    }
    if (threadIdx.x == 0) {
        const float inv = 1.0f / (float)(CPG * HWDIM);
        float mean = sh_s[0] * inv;
        float var  = sh_ss[0] * inv - mean * mean;
        g_mean[bg] = mean;
        g_rstd[bg] = rsqrtf(var + 1e-5f);
    }
}

// ---------------------------------------------------------------------------
// 2. Apply GroupNorm
// ---------------------------------------------------------------------------
__global__ void gn_apply_kernel(const float* __restrict__ x,
                                const float* __restrict__ w,
                                const float* __restrict__ bias) {
    int i4 = blockIdx.x * blockDim.x + threadIdx.x;
    const int total4 = BATCH * CDIM * HWDIM / 4;
    if (i4 >= total4) return;
    int e  = i4 * 4;
    int c  = (e / HWDIM) % CDIM;
    int bg = e / (CPG * HWDIM);
    float mean = g_mean[bg], rstd = g_rstd[bg];
    float sw = w[c] * rstd;
    float sb = bias[c] - mean * sw;
    float4 v = reinterpret_cast<const float4*>(x)[i4];
    float4 o;
    o.x = v.x * sw + sb;
    o.y = v.y * sw + sb;
    o.z = v.z * sw + sb;
    o.w = v.w * sw + sb;
    reinterpret_cast<float4*>(g_xn)[i4] = o;
}

// ---------------------------------------------------------------------------
// 3/5. Batched GEMM (fp32 SIMT)
// ---------------------------------------------------------------------------
template <int OTOT, bool RESID>
__global__ void __launch_bounds__(256) gemm_kernel(const float* __restrict__ W,
                                                   const float* __restrict__ bias,
                                                   const float* __restrict__ X,
                                                   float* __restrict__ Out,
                                                   const float* __restrict__ resid) {
    int b = blockIdx.z;
    const float* Xb = X + (size_t)b * CDIM * HWDIM;
    float* Ob = Out + (size_t)b * OTOT * HWDIM;
    int o0 = blockIdx.y * 64;
    int t0 = blockIdx.x * 64;
    __shared__ float As[16][64];
    __shared__ float Bs[16][68];
    float acc[4][4];
#pragma unroll
    for (int i = 0; i < 4; i++)
#pragma unroll
        for (int j = 0; j < 4; j++) acc[i][j] = 0.f;

    int tid = threadIdx.x;
    int tx = tid & 15, ty = tid >> 4;

    for (int k0 = 0; k0 < CDIM; k0 += 16) {
#pragma unroll 4
        for (int i = tid; i < 64 * 16; i += 256) {
            int o = i >> 4, k = i & 15;
            As[k][o] = W[(size_t)(o0 + o) * CDIM + k0 + k];
        }
#pragma unroll 4
        for (int i = tid; i < 16 * 64; i += 256) {
            int k = i >> 6, t = i & 63;
            Bs[k][t] = Xb[(size_t)(k0 + k) * HWDIM + t0 + t];
        }
        __syncthreads();
#pragma unroll
        for (int k = 0; k < 16; k++) {
            float a[4], bb[4];
#pragma unroll
            for (int i = 0; i < 4; i++) a[i] = As[k][ty * 4 + i];
#pragma unroll
            for (int j = 0; j < 4; j++) bb[j] = Bs[k][tx * 4 + j];
#pragma unroll
            for (int i = 0; i < 4; i++)
#pragma unroll
                for (int j = 0; j < 4; j++) acc[i][j] += a[i] * bb[j];
        }
        __syncthreads();
    }

#pragma unroll
    for (int i = 0; i < 4; i++) {
        int o = o0 + ty * 4 + i;
        float bo = bias[o];
#pragma unroll
        for (int j = 0; j < 4; j++) {
            int t = t0 + tx * 4 + j;
            float v = acc[i][j] + bo;
            if (RESID) v += resid[(size_t)b * CDIM * HWDIM + (size_t)o * HWDIM + t];
            Ob[(size_t)o * HWDIM + t] = v;
        }
    }
}

// ---------------------------------------------------------------------------
// 4. Flash attention, fp16 m16n8k16 mma + ldmatrix, 256 threads, 8 warps x
//    32 queries = 256 q/CTA. 64-key tiles, cp.async staging pipeline.
//    smem layout (bytes):
//      [0, 32768)       p_s   : 256 q rows x 128B (64 keys fp16), XOR-swz
//      [32768, 36864)   kf    : 64 key rows x 64B (32 ch fp16), XOR-swz
//      [36864, 40960)   vf    : 32 ch rows x 128B (64 keys fp16), XOR-swz
//      [40960, 49664)   stage_k[32][68] fp32
//      [49664, 58368)   stage_v[32][68] fp32
// ---------------------------------------------------------------------------
#define PS_OFF   0
#define KF_OFF   32768
#define VF_OFF   36864
#define STGK_OFF 40960
#define STGV_OFF 49664
#define ATTN_SMEM_BYTES 58368
#define STG_LD 68
#define NTILE (HWDIM / 64)

__global__ void __launch_bounds__(256) attn_mma_kernel(const float* __restrict__ qkv,
                                                       float* __restrict__ att) {
    extern __shared__ char smem[];
    uint32_t smem_u;
    asm("{ .reg .u64 t; cvta.to.shared.u64 t, %1; cvt.u32.u64 %0, t; }"
        : "=r"(smem_u) : "l"(smem));
    const uint32_t ps_u  = smem_u + PS_OFF;
    const uint32_t kf_u  = smem_u + KF_OFF;
    const uint32_t vf_u  = smem_u + VF_OFF;
    const uint32_t stgk_u = smem_u + STGK_OFF;
    const uint32_t stgv_u = smem_u + STGV_OFF;
    float* stage_k = (float*)(smem + STGK_OFF);
    float* stage_v = (float*)(smem + STGV_OFF);

    const int b = blockIdx.z, h = blockIdx.y;
    const int q0 = blockIdx.x * 256;
    const int tid = threadIdx.x;
    const int warp = tid >> 5, lane = tid & 31;
    const int lr = lane >> 2;    // 0..7
    const int lc = lane & 3;     // 0..3
    const int qbase = warp * 32;

    const float* Qb = qkv + ((size_t)b * OC + h * HD) * HWDIM;
    const float* Kb = Qb + (size_t)CDIM * HWDIM;
    const float* Vb = Qb + (size_t)2 * CDIM * HWDIM;
    const float scale = 0.088388347648318447f * 1.4426950408889634f;  // C^-0.5 * log2(e)

    // staging copy indices
    const int s_ch0 = tid >> 4;
    const int s_k40 = (tid & 15) * 4;
    // scatter indices
    const int sk_key = tid & 63, sk_g = tid >> 6;   // K: (key, ch-group)
    const int sv_ch  = tid & 31, sv_g = tid >> 5;   // V: (ch, key-group)

    // ---- stage tile 0 ----
    cpa16(stgk_u + (s_ch0 * STG_LD + s_k40) * 4, Kb + (size_t)s_ch0 * HWDIM + s_k40);
    cpa16(stgv_u + (s_ch0 * STG_LD + s_k40) * 4, Vb + (size_t)s_ch0 * HWDIM + s_k40);
    {
        int ch1 = s_ch0 + 16;
        cpa16(stgk_u + (ch1 * STG_LD + s_k40) * 4, Kb + (size_t)ch1 * HWDIM + s_k40);
        cpa16(stgv_u + (ch1 * STG_LD + s_k40) * 4, Vb + (size_t)ch1 * HWDIM + s_k40);
    }
    asm volatile("cp.async.commit_group;" ::: "memory");

    // ---- Q fragments (fp16), loaded once from gmem ----
    uint32_t qa[2][2][4];
#pragma unroll
    for (int mf = 0; mf < 2; mf++) {
        int qrow = q0 + qbase + mf * 16 + lr;
#pragma unroll
        for (int ks = 0; ks < 2; ks++) {
            int c0 = 2 * lc + 16 * ks;
            qa[mf][ks][0] = packh2(Qb[(size_t)c0 * HWDIM + qrow] * scale,
                                   Qb[(size_t)(c0 + 1) * HWDIM + qrow] * scale);
            qa[mf][ks][1] = packh2(Qb[(size_t)c0 * HWDIM + qrow + 8] * scale,
                                   Qb[(size_t)(c0 + 1) * HWDIM + qrow + 8] * scale);
            qa[mf][ks][2] = packh2(Qb[(size_t)(c0 + 8) * HWDIM + qrow] * scale,
                                   Qb[(size_t)(c0 + 9) * HWDIM + qrow] * scale);
            qa[mf][ks][3] = packh2(Qb[(size_t)(c0 + 8) * HWDIM + qrow + 8] * scale,
                                   Qb[(size_t)(c0 + 9) * HWDIM + qrow + 8] * scale);
        }
    }

    asm volatile("cp.async.wait_group 0;" ::: "memory");
    __syncthreads();

    // ---- scatter tile 0 into kf/vf (fp32 -> fp16, swizzled) ----
    {
#pragma unroll
        for (int dummy = 0; dummy < 1; dummy++) {
            float f[8];
#pragma unroll
            for (int i = 0; i < 8; i++)
                f[i] = stage_k[(8 * sk_g + i) * STG_LD + sk_key];
            sts128u(kf_u + sk_key * 64 + ((sk_g ^ ((sk_key >> 1) & 3)) << 4),
                    packh2(f[0], f[1]), packh2(f[2], f[3]),
                    packh2(f[4], f[5]), packh2(f[6], f[7]));
            float4 a = *(const float4*)&stage_v[sv_ch * STG_LD + 8 * sv_g];
            float4 c = *(const float4*)&stage_v[sv_ch * STG_LD + 8 * sv_g + 4];
            sts128u(vf_u + sv_ch * 128 + ((sv_g ^ (sv_ch & 7)) << 4),
                    packh2(a.x, a.y), packh2(a.z, a.w),
                    packh2(c.x, c.y), packh2(c.z, c.w));
        }
    }
    __syncthreads();

    float l_i[2][2] = {{0.f, 0.f}, {0.f, 0.f}};
    float oacc[2][4][4];
#pragma unroll
    for (int mf = 0; mf < 2; mf++)
#pragma unroll
        for (int nf = 0; nf < 4; nf++)
#pragma unroll
            for (int c = 0; c < 4; c++) oacc[mf][nf][c] = 0.f;

    const int r8 = lane & 7, j8 = lane >> 3;  // ldmatrix lane roles

    for (int t = 0; t < NTILE; t++) {
        // ---- stage tile t+1 ----
        if (t < NTILE - 1) {
            const int j0n = (t + 1) * 64;
            cpa16(stgk_u + (s_ch0 * STG_LD + s_k40) * 4,
                  Kb + (size_t)s_ch0 * HWDIM + j0n + s_k40);
            cpa16(stgv_u + (s_ch0 * STG_LD + s_k40) * 4,
                  Vb + (size_t)s_ch0 * HWDIM + j0n + s_k40);
            int ch1 = s_ch0 + 16;
            cpa16(stgk_u + (ch1 * STG_LD + s_k40) * 4,
                  Kb + (size_t)ch1 * HWDIM + j0n + s_k40);
            cpa16(stgv_u + (ch1 * STG_LD + s_k40) * 4,
                  Vb + (size_t)ch1 * HWDIM + j0n + s_k40);
            asm volatile("cp.async.commit_group;" ::: "memory");
        }

        // ---- S = Q @ K^T : 32q x 64 keys per warp ----
        float sacc[2][8][4];
#pragma unroll
        for (int mf = 0; mf < 2; mf++)
#pragma unroll
            for (int nf = 0; nf < 8; nf++)
#pragma unroll
                for (int c = 0; c < 4; c++) sacc[mf][nf][c] = 0.f;

#pragma unroll
        for (int nf = 0; nf < 8; nf++) {
            uint32_t kb[4];
            int row = nf * 8 + r8;
            ldm4(kb, kf_u + row * 64 + ((j8 ^ ((row >> 1) & 3)) << 4));
#pragma unroll
            for (int mf = 0; mf < 2; mf++) {
                mma16(sacc[mf][nf], qa[mf][0], kb[0], kb[1]);
                mma16(sacc[mf][nf], qa[mf][1], kb[2], kb[3]);
            }
        }

        // ---- softmax numerator (exp2 domain, no max) ----
#pragma unroll
        for (int mf = 0; mf < 2; mf++)
#pragma unroll
            for (int ri = 0; ri < 2; ri++) {
                float sum = 0.f;
#pragma unroll
                for (int nf = 0; nf < 8; nf++) {
                    float p0 = exp2f(sacc[mf][nf][2 * ri]);
                    float p1 = exp2f(sacc[mf][nf][2 * ri + 1]);
                    sacc[mf][nf][2 * ri] = p0;
                    sacc[mf][nf][2 * ri + 1] = p1;
                    sum += p0 + p1;
                }
                sum += __shfl_xor_sync(0xffffffffu, sum, 1);
                sum += __shfl_xor_sync(0xffffffffu, sum, 2);
                l_i[mf][ri] += sum;
            }

        // ---- P -> smem (fp16, swizzled); per-warp private rows ----
        __syncwarp();
#pragma unroll
        for (int mf = 0; mf < 2; mf++) {
            int row = qbase + mf * 16 + lr;
#pragma unroll
            for (int nf = 0; nf < 8; nf++) {
                uint32_t base = ps_u + (((nf ^ lr) & 7) << 4) + (lc << 2);
                st32(base + row * 128, packh2(sacc[mf][nf][0], sacc[mf][nf][1]));
                st32(base + (row + 8) * 128, packh2(sacc[mf][nf][2], sacc[mf][nf][3]));
            }
        }
        __syncwarp();

        // ---- V b-frags via ldmatrix ----
        uint32_t vb[4][2][4];
#pragma unroll
        for (int nf = 0; nf < 4; nf++)
#pragma unroll
            for (int l = 0; l < 2; l++) {
                int row = nf * 8 + r8;
                int g = l * 4 + j8;
                ldm4(vb[nf][l], vf_u + row * 128 + ((g ^ r8) << 4));
            }

        // ---- O += P @ V ----
#pragma unroll
        for (int mf = 0; mf < 2; mf++) {
#pragma unroll
            for (int kq = 0; kq < 4; kq++) {
                uint32_t pa[4];
                int row = qbase + mf * 16 + ((j8 & 1) << 3) + r8;
                int g = kq * 2 + (j8 >> 1);
                ldm4(pa, ps_u + row * 128 + ((g ^ r8) << 4));
                uint32_t* vv;
#pragma unroll
                for (int nf = 0; nf < 4; nf++) {
                    vv = vb[nf][kq >> 1];
                    mma16(oacc[mf][nf], pa, vv[2 * (kq & 1)], vv[2 * (kq & 1) + 1]);
                }
            }
        }

        // ---- rotate staged tile into kf/vf ----
        if (t < NTILE - 1) {
            asm volatile("cp.async.wait_group 0;" ::: "memory");
            __syncthreads();
            float f[8];
#pragma unroll
            for (int i = 0; i < 8; i++)
                f[i] = stage_k[(8 * sk_g + i) * STG_LD + sk_key];
            sts128u(kf_u + sk_key * 64 + ((sk_g ^ ((sk_key >> 1) & 3)) << 4),
                    packh2(f[0], f[1]), packh2(f[2], f[3]),
                    packh2(f[4], f[5]), packh2(f[6], f[7]));
            float4 a = *(const float4*)&stage_v[sv_ch * STG_LD + 8 * sv_g];
            float4 c = *(const float4*)&stage_v[sv_ch * STG_LD + 8 * sv_g + 4];
            sts128u(vf_u + sv_ch * 128 + ((sv_g ^ (sv_ch & 7)) << 4),
                    packh2(a.x, a.y), packh2(a.z, a.w),
                    packh2(c.x, c.y), packh2(c.z, c.w));
            __syncthreads();
        }
    }

    // ---- epilogue ----
#pragma unroll
    for (int mf = 0; mf < 2; mf++)
#pragma unroll
        for (int ri = 0; ri < 2; ri++) {
            float inv = 1.f / l_i[mf][ri];
            int q = q0 + qbase + mf * 16 + lr + 8 * ri;
#pragma unroll
            for (int nf = 0; nf < 4; nf++)
#pragma unroll
                for (int j = 0; j < 2; j++) {
                    int ch = nf * 8 + 2 * lc + j;
                    att[((size_t)b * CDIM + h * HD + ch) * HWDIM + q] =
                        oacc[mf][nf][2 * ri + j] * inv;
                }
        }
}

// ---------------------------------------------------------------------------
// Launch
// ---------------------------------------------------------------------------
extern "C" void kernel_launch(void* const* d_in, const int* in_sizes, int n_in,
                              void* d_out, int out_size) {
    const float* x      = (const float*)d_in[0];
    const float* gn_w   = (const float*)d_in[1];
    const float* gn_b   = (const float*)d_in[2];
    const float* qkv_w  = (const float*)d_in[3];
    const float* qkv_b  = (const float*)d_in[4];
    const float* proj_w = (const float*)d_in[5];
    const float* proj_b = (const float*)d_in[6];
    float* out = (float*)d_out;

    float *xn_p, *qkv_p, *att_p;
    cudaGetSymbolAddress((void**)&xn_p, g_xn);
    cudaGetSymbolAddress((void**)&qkv_p, g_qkv);
    cudaGetSymbolAddress((void**)&att_p, g_att);

    static bool attr_set = false;
    if (!attr_set) {
        cudaFuncSetAttribute(attn_mma_kernel,
                             cudaFuncAttributeMaxDynamicSharedMemorySize,
                             ATTN_SMEM_BYTES);
        attr_set = true;
    }

    gn_stats_kernel<<<BATCH * NGROUP, 256>>>(x);
    gn_apply_kernel<<<(BATCH * CDIM * HWDIM / 4 + 255) / 256, 256>>>(x, gn_w, gn_b);
    gemm_kernel<OC, false><<<dim3(HWDIM / 64, OC / 64, BATCH), 256>>>(
        qkv_w, qkv_b, xn_p, qkv_p, nullptr);
    attn_mma_kernel<<<dim3(HWDIM / 256, NH, BATCH), 256, ATTN_SMEM_BYTES>>>(qkv_p, att_p);
    gemm_kernel<CDIM, true><<<dim3(HWDIM / 64, CDIM / 64, BATCH), 256>>>(
        proj_w, proj_b, att_p, out, xn_p);
}

// round 11
// speedup vs baseline: 3.9966x; 1.6649x over previous
#include <cuda_runtime.h>
#include <cuda_fp16.h>
#include <stdint.h>
#include <math.h>

#define BATCH 4
#define CDIM 128
#define HWDIM 4096
#define NGROUP 8
#define CPG 16
#define NH 4
#define HD 32
#define OC 384   // 3*C

// Scratch (allocation-free: device globals)
__device__ float g_xn[BATCH * CDIM * HWDIM];                       // fp32 residual
__device__ __align__(16) __half g_xnh[BATCH * CDIM * HWDIM];       // fp16 [b][c][t]
__device__ __align__(16) __half g_qh[BATCH * HWDIM * CDIM];        // fp16 [b][t][128], pre-scaled Q
__device__ __align__(16) __half g_kvh[BATCH * 2 * CDIM * HWDIM];   // fp16 [b][ch 0..255][t]: K then V
__device__ float g_att[BATCH * CDIM * HWDIM];
__device__ float g_mean[BATCH * NGROUP];
__device__ float g_rstd[BATCH * NGROUP];

__device__ __forceinline__ void mma16(float* d, const uint32_t* a, uint32_t b0, uint32_t b1) {
    asm volatile(
        "mma.sync.aligned.m16n8k16.row.col.f32.f16.f16.f32 "
        "{%0,%1,%2,%3},{%4,%5,%6,%7},{%8,%9},{%0,%1,%2,%3};\n"
        : "+f"(d[0]), "+f"(d[1]), "+f"(d[2]), "+f"(d[3])
        : "r"(a[0]), "r"(a[1]), "r"(a[2]), "r"(a[3]), "r"(b0), "r"(b1));
}

__device__ __forceinline__ void ldm4(uint32_t* r, uint32_t addr) {
    asm volatile("ldmatrix.sync.aligned.m8n8.x4.shared.b16 {%0,%1,%2,%3}, [%4];"
                 : "=r"(r[0]), "=r"(r[1]), "=r"(r[2]), "=r"(r[3]) : "r"(addr));
}

__device__ __forceinline__ void ldm4t(uint32_t* r, uint32_t addr) {
    asm volatile("ldmatrix.sync.aligned.m8n8.x4.trans.shared.b16 {%0,%1,%2,%3}, [%4];"
                 : "=r"(r[0]), "=r"(r[1]), "=r"(r[2]), "=r"(r[3]) : "r"(addr));
}

__device__ __forceinline__ uint32_t packh2(float lo, float hi) {
    __half2 h = __floats2half2_rn(lo, hi);
    return *reinterpret_cast<uint32_t*>(&h);
}

__device__ __forceinline__ uint32_t h2ex2(uint32_t x) {
    uint32_t r;
    asm("ex2.approx.f16x2 %0, %1;" : "=r"(r) : "r"(x));
    return r;
}

__device__ __forceinline__ void cpa16(uint32_t dst, const void* src) {
    asm volatile("cp.async.cg.shared.global [%0], [%1], 16;" :: "r"(dst), "l"(src));
}

__device__ __forceinline__ void st32(uint32_t addr, uint32_t v) {
    asm volatile("st.shared.u32 [%0], %1;" :: "r"(addr), "r"(v));
}

__device__ __forceinline__ void sts128u(uint32_t addr, uint32_t a, uint32_t b,
                                        uint32_t c, uint32_t d) {
    asm volatile("st.shared.v4.u32 [%0], {%1,%2,%3,%4};"
                 :: "r"(addr), "r"(a), "r"(b), "r"(c), "r"(d));
}

// ---------------------------------------------------------------------------
// 1. GroupNorm statistics
// ---------------------------------------------------------------------------
__global__ void gn_stats_kernel(const float* __restrict__ x) {
    int bg = blockIdx.x;
    const float4* p = reinterpret_cast<const float4*>(x + (size_t)bg * CPG * HWDIM);
    const int n4 = CPG * HWDIM / 4;
    float s = 0.f, ss = 0.f;
    for (int i = threadIdx.x; i < n4; i += blockDim.x) {
        float4 v = p[i];
        s  += v.x + v.y + v.z + v.w;
        ss += v.x * v.x + v.y * v.y + v.z * v.z + v.w * v.w;
    }
    __shared__ float sh_s[256], sh_ss[256];
    sh_s[threadIdx.x] = s;
    sh_ss[threadIdx.x] = ss;
    __syncthreads();
    for (int off = 128; off > 0; off >>= 1) {
        if (threadIdx.x < off) {
            sh_s[threadIdx.x]  += sh_s[threadIdx.x + off];
            sh_ss[threadIdx.x] += sh_ss[threadIdx.x + off];
        }
        __syncthreads();
    }
    if (threadIdx.x == 0) {
        const float inv = 1.0f / (float)(CPG * HWDIM);
        float mean = sh_s[0] * inv;
        float var  = sh_ss[0] * inv - mean * mean;
        g_mean[bg] = mean;
        g_rstd[bg] = rsqrtf(var + 1e-5f);
    }
}

// ---------------------------------------------------------------------------
// 2. Apply GroupNorm: fp32 out (residual) + fp16 out (GEMM input)
// ---------------------------------------------------------------------------
__global__ void gn_apply_kernel(const float* __restrict__ x,
                                const float* __restrict__ w,
                                const float* __restrict__ bias) {
    int i4 = blockIdx.x * blockDim.x + threadIdx.x;
    const int total4 = BATCH * CDIM * HWDIM / 4;
    if (i4 >= total4) return;
    int e  = i4 * 4;
    int c  = (e / HWDIM) % CDIM;
    int bg = e / (CPG * HWDIM);
    float mean = g_mean[bg], rstd = g_rstd[bg];
    float sw = w[c] * rstd;
    float sb = bias[c] - mean * sw;
    float4 v = reinterpret_cast<const float4*>(x)[i4];
    float4 o;
    o.x = v.x * sw + sb;
    o.y = v.y * sw + sb;
    o.z = v.z * sw + sb;
    o.w = v.w * sw + sb;
    reinterpret_cast<float4*>(g_xn)[i4] = o;
    reinterpret_cast<__half2*>(g_xnh)[i4 * 2]     = __floats2half2_rn(o.x, o.y);
    reinterpret_cast<__half2*>(g_xnh)[i4 * 2 + 1] = __floats2half2_rn(o.z, o.w);
}

// ---------------------------------------------------------------------------
// 3. QKV GEMM, fp16 tensor cores. Out = W @ xn + bias.
//    A = xn^T (m=t, k=c) via ldmatrix.trans from xs[c][t];
//    B = W (n=o, k=c) via ldmatrix from ws[o][c]. fp32 accum.
//    Q rows (o<128) written pre-scaled fp16 to g_qh[t][o];
//    K/V rows written fp16 to g_kvh[o-128][t].
// ---------------------------------------------------------------------------
#define QKV_SMEM (16384 + 32768)

__global__ void __launch_bounds__(256) qkv_h_kernel(const float* __restrict__ W,
                                                    const float* __restrict__ bias) {
    extern __shared__ char qs[];
    uint32_t ws_u, xs_u;
    asm("{ .reg .u64 t; cvta.to.shared.u64 t, %1; cvt.u32.u64 %0, t; }"
        : "=r"(ws_u) : "l"(qs));
    xs_u = ws_u + 16384;

    const int b = blockIdx.z;
    const int ob0 = blockIdx.y * 64;
    const int t0 = blockIdx.x * 128;
    const int tid = threadIdx.x, warp = tid >> 5, lane = tid & 31;
    const int lr = lane >> 2, lc = lane & 3, r8 = lane & 7, j8 = lane >> 3;

    // ---- W tile: [64 o][128 c] fp32 -> fp16, swizzled 16B groups ----
    {
        int row = tid >> 2;
#pragma unroll
        for (int i = 0; i < 4; i++) {
            int g = (tid & 3) * 4 + i;
            const float* wp = W + (size_t)(ob0 + row) * CDIM + g * 8;
            float4 wa = *(const float4*)wp;
            float4 wb = *(const float4*)(wp + 4);
            sts128u(ws_u + row * 256 + ((g ^ (row & 7)) << 4),
                    packh2(wa.x, wa.y), packh2(wa.z, wa.w),
                    packh2(wb.x, wb.y), packh2(wb.z, wb.w));
        }
    }
    // ---- X tile: [128 c][128 t] fp16 direct via cp.async ----
    {
        int tg = tid & 15, c0 = (tid >> 4) * 8;
        const __half* xp = g_xnh + (size_t)b * CDIM * HWDIM;
#pragma unroll
        for (int j = 0; j < 8; j++) {
            int c = c0 + j;
            cpa16(xs_u + c * 256 + ((tg ^ (c & 7)) << 4),
                  xp + (size_t)c * HWDIM + t0 + tg * 8);
        }
        asm volatile("cp.async.commit_group;" ::: "memory");
    }
    asm volatile("cp.async.wait_group 0;" ::: "memory");
    __syncthreads();

    const int wm = warp & 1, wn = warp >> 1;  // t-half, o-quarter
    float acc[4][2][4];
#pragma unroll
    for (int mi = 0; mi < 4; mi++)
#pragma unroll
        for (int n8 = 0; n8 < 2; n8++)
#pragma unroll
            for (int c = 0; c < 4; c++) acc[mi][n8][c] = 0.f;

#pragma unroll
    for (int ks = 0; ks < 4; ks++) {  // k = 32 per step
        uint32_t bf[2][4];
#pragma unroll
        for (int n8 = 0; n8 < 2; n8++) {
            int row = wn * 16 + n8 * 8 + r8;
            ldm4(bf[n8], ws_u + row * 256 + (((ks * 4 + j8) ^ (row & 7)) << 4));
        }
        uint32_t af[4][2][4];
#pragma unroll
        for (int mi = 0; mi < 4; mi++)
#pragma unroll
            for (int kh = 0; kh < 2; kh++) {
                int c_row = ks * 32 + kh * 16 + (lane & 7) + ((lane >> 4) & 1) * 8;
                int tg = wm * 8 + mi * 2 + ((lane >> 3) & 1);
                ldm4t(af[mi][kh], xs_u + c_row * 256 + ((tg ^ (c_row & 7)) << 4));
            }
#pragma unroll
        for (int mi = 0; mi < 4; mi++)
#pragma unroll
            for (int n8 = 0; n8 < 2; n8++) {
                mma16(acc[mi][n8], af[mi][0], bf[n8][0], bf[n8][1]);
                mma16(acc[mi][n8], af[mi][1], bf[n8][2], bf[n8][3]);
            }
    }

    // ---- epilogue ----
    const float QSC = 0.088388347648318447f * 1.4426950408889634f;  // C^-0.5 * log2(e)
#pragma unroll
    for (int mi = 0; mi < 4; mi++) {
        int t = t0 + wm * 64 + mi * 16 + lr;
#pragma unroll
        for (int n8 = 0; n8 < 2; n8++) {
            int o = ob0 + wn * 16 + n8 * 8 + 2 * lc;
            float b0 = bias[o], b1 = bias[o + 1];
            float v0 = acc[mi][n8][0] + b0, v1 = acc[mi][n8][1] + b1;
            float v2 = acc[mi][n8][2] + b0, v3 = acc[mi][n8][3] + b1;
            if (ob0 < 128) {  // Q: [t][o], pre-scaled
                *(__half2*)(g_qh + ((size_t)b * HWDIM + t) * CDIM + o) =
                    __floats2half2_rn(v0 * QSC, v1 * QSC);
                *(__half2*)(g_qh + ((size_t)b * HWDIM + t + 8) * CDIM + o) =
                    __floats2half2_rn(v2 * QSC, v3 * QSC);
            } else {          // K/V: [ch][t]
                __half* kv = g_kvh + (size_t)b * 2 * CDIM * HWDIM;
                kv[(size_t)(o - 128) * HWDIM + t]     = __float2half(v0);
                kv[(size_t)(o - 127) * HWDIM + t]     = __float2half(v1);
                kv[(size_t)(o - 128) * HWDIM + t + 8] = __float2half(v2);
                kv[(size_t)(o - 127) * HWDIM + t + 8] = __float2half(v3);
            }
        }
    }
}

// ---------------------------------------------------------------------------
// 5. Projection GEMM (fp32 SIMT) + bias + residual
// ---------------------------------------------------------------------------
__global__ void __launch_bounds__(256) proj_kernel(const float* __restrict__ W,
                                                   const float* __restrict__ bias,
                                                   const float* __restrict__ X,
                                                   float* __restrict__ Out,
                                                   const float* __restrict__ resid) {
    int b = blockIdx.z;
    const float* Xb = X + (size_t)b * CDIM * HWDIM;
    float* Ob = Out + (size_t)b * CDIM * HWDIM;
    int o0 = blockIdx.y * 64;
    int t0 = blockIdx.x * 64;
    __shared__ float As[16][64];
    __shared__ float Bs[16][68];
    float acc[4][4];
#pragma unroll
    for (int i = 0; i < 4; i++)
#pragma unroll
        for (int j = 0; j < 4; j++) acc[i][j] = 0.f;

    int tid = threadIdx.x;
    int tx = tid & 15, ty = tid >> 4;

    for (int k0 = 0; k0 < CDIM; k0 += 16) {
#pragma unroll 4
        for (int i = tid; i < 64 * 16; i += 256) {
            int o = i >> 4, k = i & 15;
            As[k][o] = W[(size_t)(o0 + o) * CDIM + k0 + k];
        }
#pragma unroll 4
        for (int i = tid; i < 16 * 64; i += 256) {
            int k = i >> 6, t = i & 63;
            Bs[k][t] = Xb[(size_t)(k0 + k) * HWDIM + t0 + t];
        }
        __syncthreads();
#pragma unroll
        for (int k = 0; k < 16; k++) {
            float a[4], bb[4];
#pragma unroll
            for (int i = 0; i < 4; i++) a[i] = As[k][ty * 4 + i];
#pragma unroll
            for (int j = 0; j < 4; j++) bb[j] = Bs[k][tx * 4 + j];
#pragma unroll
            for (int i = 0; i < 4; i++)
#pragma unroll
                for (int j = 0; j < 4; j++) acc[i][j] += a[i] * bb[j];
        }
        __syncthreads();
    }

#pragma unroll
    for (int i = 0; i < 4; i++) {
        int o = o0 + ty * 4 + i;
        float bo = bias[o];
#pragma unroll
        for (int j = 0; j < 4; j++) {
            int t = t0 + tx * 4 + j;
            float v = acc[i][j] + bo;
            v += resid[(size_t)b * CDIM * HWDIM + (size_t)o * HWDIM + t];
            Ob[(size_t)o * HWDIM + t] = v;
        }
    }
}

// ---------------------------------------------------------------------------
// 4. Flash attention, fp16 mma + ldmatrix, fp16 inputs, f16x2 exp2.
//    256 threads, 8 warps x 32 queries = 256 q/CTA. 64-key tiles.
//    smem layout (bytes):
//      [0, 32768)       p_s   : 256 q rows x 128B, XOR-swz
//      [32768, 36864)   kf    : 64 key rows x 64B (32 ch fp16), XOR-swz
//      [36864, 40960)   vf    : 32 ch rows x 128B (64 keys fp16), XOR-swz
//      [40960, 45568)   stage_k half[32][72]
//      [45568, 50176)   stage_v half[32][72]
// ---------------------------------------------------------------------------
#define PS_OFF   0
#define KF_OFF   32768
#define VF_OFF   36864
#define STGK_OFF 40960
#define STGV_OFF 45568
#define ATTN_SMEM_BYTES 50176
#define NTILE (HWDIM / 64)

__global__ void __launch_bounds__(256) attn_mma_kernel(float* __restrict__ att) {
    extern __shared__ char smem[];
    uint32_t smem_u;
    asm("{ .reg .u64 t; cvta.to.shared.u64 t, %1; cvt.u32.u64 %0, t; }"
        : "=r"(smem_u) : "l"(smem));
    const uint32_t ps_u   = smem_u + PS_OFF;
    const uint32_t kf_u   = smem_u + KF_OFF;
    const uint32_t vf_u   = smem_u + VF_OFF;
    const uint32_t stgk_u = smem_u + STGK_OFF;
    const uint32_t stgv_u = smem_u + STGV_OFF;
    const __half* stage_k = (const __half*)(smem + STGK_OFF);
    const char*   stage_vb = smem + STGV_OFF;

    const int b = blockIdx.z, h = blockIdx.y;
    const int q0 = blockIdx.x * 256;
    const int tid = threadIdx.x;
    const int warp = tid >> 5, lane = tid & 31;
    const int lr = lane >> 2;    // 0..7
    const int lc = lane & 3;     // 0..3
    const int qbase = warp * 32;

    const __half* Qh = g_qh + (size_t)b * HWDIM * CDIM;
    const __half* Kh = g_kvh + ((size_t)b * 2 * CDIM + h * HD) * HWDIM;
    const __half* Vh = Kh + (size_t)CDIM * HWDIM;

    // staging chunk indices: 1 chunk of K + 1 of V per thread per tile
    const int s_kg = tid & 7;        // key-group of 8
    const int s_ch = tid >> 3;       // ch 0..31
    // K scatter indices
    const int sk_key = tid & 63, sk_g = tid >> 6;
    // V scatter indices
    const int sv_ch = tid & 31, sv_g = tid >> 5;

    // ---- stage tile 0 ----
    cpa16(stgk_u + (s_ch * 72 + s_kg * 8) * 2, Kh + (size_t)s_ch * HWDIM + s_kg * 8);
    cpa16(stgv_u + (s_ch * 72 + s_kg * 8) * 2, Vh + (size_t)s_ch * HWDIM + s_kg * 8);
    asm volatile("cp.async.commit_group;" ::: "memory");

    // ---- Q fragments (fp16 pre-scaled, half2 loads) ----
    uint32_t qa[2][2][4];
#pragma unroll
    for (int mf = 0; mf < 2; mf++) {
        int qrow = q0 + qbase + mf * 16 + lr;
#pragma unroll
        for (int ks = 0; ks < 2; ks++) {
            int cc = h * HD + 2 * lc + 16 * ks;
            qa[mf][ks][0] = *(const uint32_t*)(Qh + (size_t)qrow * CDIM + cc);
            qa[mf][ks][1] = *(const uint32_t*)(Qh + (size_t)(qrow + 8) * CDIM + cc);
            qa[mf][ks][2] = *(const uint32_t*)(Qh + (size_t)qrow * CDIM + cc + 8);
            qa[mf][ks][3] = *(const uint32_t*)(Qh + (size_t)(qrow + 8) * CDIM + cc + 8);
        }
    }

    asm volatile("cp.async.wait_group 0;" ::: "memory");
    __syncthreads();

    // ---- scatter tile 0 into kf/vf ----
    {
        const unsigned short* sk = (const unsigned short*)stage_k;
        unsigned short hh[8];
#pragma unroll
        for (int i = 0; i < 8; i++)
            hh[i] = sk[(8 * sk_g + i) * 72 + sk_key];
        sts128u(kf_u + sk_key * 64 + ((sk_g ^ ((sk_key >> 1) & 3)) << 4),
                (uint32_t)hh[0] | ((uint32_t)hh[1] << 16),
                (uint32_t)hh[2] | ((uint32_t)hh[3] << 16),
                (uint32_t)hh[4] | ((uint32_t)hh[5] << 16),
                (uint32_t)hh[6] | ((uint32_t)hh[7] << 16));
        uint4 v = *(const uint4*)(stage_vb + sv_ch * 144 + sv_g * 16);
        sts128u(vf_u + sv_ch * 128 + ((sv_g ^ (sv_ch & 7)) << 4), v.x, v.y, v.z, v.w);
    }
    __syncthreads();

    float l_i[2][2] = {{0.f, 0.f}, {0.f, 0.f}};
    float oacc[2][4][4];
#pragma unroll
    for (int mf = 0; mf < 2; mf++)
#pragma unroll
        for (int nf = 0; nf < 4; nf++)
#pragma unroll
            for (int c = 0; c < 4; c++) oacc[mf][nf][c] = 0.f;

    const int r8 = lane & 7, j8 = lane >> 3;

    for (int t = 0; t < NTILE; t++) {
        // ---- stage tile t+1 ----
        if (t < NTILE - 1) {
            const int j0n = (t + 1) * 64;
            cpa16(stgk_u + (s_ch * 72 + s_kg * 8) * 2,
                  Kh + (size_t)s_ch * HWDIM + j0n + s_kg * 8);
            cpa16(stgv_u + (s_ch * 72 + s_kg * 8) * 2,
                  Vh + (size_t)s_ch * HWDIM + j0n + s_kg * 8);
            asm volatile("cp.async.commit_group;" ::: "memory");
        }

        // ---- S = Q @ K^T ----
        float sacc[2][8][4];
#pragma unroll
        for (int mf = 0; mf < 2; mf++)
#pragma unroll
            for (int nf = 0; nf < 8; nf++)
#pragma unroll
                for (int c = 0; c < 4; c++) sacc[mf][nf][c] = 0.f;

#pragma unroll
        for (int nf = 0; nf < 8; nf++) {
            uint32_t kb[4];
            int row = nf * 8 + r8;
            ldm4(kb, kf_u + row * 64 + ((j8 ^ ((row >> 1) & 3)) << 4));
#pragma unroll
            for (int mf = 0; mf < 2; mf++) {
                mma16(sacc[mf][nf], qa[mf][0], kb[0], kb[1]);
                mma16(sacc[mf][nf], qa[mf][1], kb[2], kb[3]);
            }
        }

        // ---- softmax numerator: f16x2 exp2, HADD2 row sums, P to smem ----
#pragma unroll
        for (int mf = 0; mf < 2; mf++) {
            uint32_t ph0[8], ph1[8];
#pragma unroll
            for (int nf = 0; nf < 8; nf++) {
                ph0[nf] = h2ex2(packh2(sacc[mf][nf][0], sacc[mf][nf][1]));
                ph1[nf] = h2ex2(packh2(sacc[mf][nf][2], sacc[mf][nf][3]));
            }
#pragma unroll
            for (int ri = 0; ri < 2; ri++) {
                const uint32_t* ph = ri ? ph1 : ph0;
                __half2 s0 = __hadd2(*(__half2*)&ph[0], *(__half2*)&ph[1]);
                __half2 s1 = __hadd2(*(__half2*)&ph[2], *(__half2*)&ph[3]);
                __half2 s2 = __hadd2(*(__half2*)&ph[4], *(__half2*)&ph[5]);
                __half2 s3 = __hadd2(*(__half2*)&ph[6], *(__half2*)&ph[7]);
                __half2 s = __hadd2(__hadd2(s0, s1), __hadd2(s2, s3));
                float2 f = __half22float2(s);
                float sum = f.x + f.y;
                sum += __shfl_xor_sync(0xffffffffu, sum, 1);
                sum += __shfl_xor_sync(0xffffffffu, sum, 2);
                l_i[mf][ri] += sum;
            }
            int row = qbase + mf * 16 + lr;
#pragma unroll
            for (int nf = 0; nf < 8; nf++) {
                uint32_t base = ps_u + (((nf ^ lr) & 7) << 4) + (lc << 2);
                st32(base + row * 128, ph0[nf]);
                st32(base + (row + 8) * 128, ph1[nf]);
            }
        }
        __syncwarp();

        // ---- V b-frags ----
        uint32_t vb[4][2][4];
#pragma unroll
        for (int nf = 0; nf < 4; nf++)
#pragma unroll
            for (int l = 0; l < 2; l++) {
                int row = nf * 8 + r8;
                int g = l * 4 + j8;
                ldm4(vb[nf][l], vf_u + row * 128 + ((g ^ r8) << 4));
            }

        // ---- O += P @ V ----
#pragma unroll
        for (int mf = 0; mf < 2; mf++) {
#pragma unroll
            for (int kq = 0; kq < 4; kq++) {
                uint32_t pa[4];
                int row = qbase + mf * 16 + ((j8 & 1) << 3) + r8;
                int g = kq * 2 + (j8 >> 1);
                ldm4(pa, ps_u + row * 128 + ((g ^ r8) << 4));
#pragma unroll
                for (int nf = 0; nf < 4; nf++) {
                    uint32_t* vv = vb[nf][kq >> 1];
                    mma16(oacc[mf][nf], pa, vv[2 * (kq & 1)], vv[2 * (kq & 1) + 1]);
                }
            }
        }

        // ---- rotate staged tile into kf/vf ----
        if (t < NTILE - 1) {
            asm volatile("cp.async.wait_group 0;" ::: "memory");
            __syncthreads();
            const unsigned short* sk = (const unsigned short*)stage_k;
            unsigned short hh[8];
#pragma unroll
            for (int i = 0; i < 8; i++)
                hh[i] = sk[(8 * sk_g + i) * 72 + sk_key];
            sts128u(kf_u + sk_key * 64 + ((sk_g ^ ((sk_key >> 1) & 3)) << 4),
                    (uint32_t)hh[0] | ((uint32_t)hh[1] << 16),
                    (uint32_t)hh[2] | ((uint32_t)hh[3] << 16),
                    (uint32_t)hh[4] | ((uint32_t)hh[5] << 16),
                    (uint32_t)hh[6] | ((uint32_t)hh[7] << 16));
            uint4 v = *(const uint4*)(stage_vb + sv_ch * 144 + sv_g * 16);
            sts128u(vf_u + sv_ch * 128 + ((sv_g ^ (sv_ch & 7)) << 4), v.x, v.y, v.z, v.w);
            __syncthreads();
        }
    }

    // ---- epilogue (fp32 att, [ch][t]) ----
#pragma unroll
    for (int mf = 0; mf < 2; mf++)
#pragma unroll
        for (int ri = 0; ri < 2; ri++) {
            float inv = 1.f / l_i[mf][ri];
            int q = q0 + qbase + mf * 16 + lr + 8 * ri;
#pragma unroll
            for (int nf = 0; nf < 4; nf++)
#pragma unroll
                for (int j = 0; j < 2; j++) {
                    int ch = nf * 8 + 2 * lc + j;
                    att[((size_t)b * CDIM + h * HD + ch) * HWDIM + q] =
                        oacc[mf][nf][2 * ri + j] * inv;
                }
        }
}

// ---------------------------------------------------------------------------
// Launch
// ---------------------------------------------------------------------------
extern "C" void kernel_launch(void* const* d_in, const int* in_sizes, int n_in,
                              void* d_out, int out_size) {
    const float* x      = (const float*)d_in[0];
    const float* gn_w   = (const float*)d_in[1];
    const float* gn_b   = (const float*)d_in[2];
    const float* qkv_w  = (const float*)d_in[3];
    const float* qkv_b  = (const float*)d_in[4];
    const float* proj_w = (const float*)d_in[5];
    const float* proj_b = (const float*)d_in[6];
    float* out = (float*)d_out;

    float *xn_p, *att_p;
    cudaGetSymbolAddress((void**)&xn_p, g_xn);
    cudaGetSymbolAddress((void**)&att_p, g_att);

    static bool attr_set = false;
    if (!attr_set) {
        cudaFuncSetAttribute(attn_mma_kernel,
                             cudaFuncAttributeMaxDynamicSharedMemorySize,
                             ATTN_SMEM_BYTES);
        cudaFuncSetAttribute(qkv_h_kernel,
                             cudaFuncAttributeMaxDynamicSharedMemorySize,
                             QKV_SMEM);
        attr_set = true;
    }

    gn_stats_kernel<<<BATCH * NGROUP, 256>>>(x);
    gn_apply_kernel<<<(BATCH * CDIM * HWDIM / 4 + 255) / 256, 256>>>(x, gn_w, gn_b);
    qkv_h_kernel<<<dim3(HWDIM / 128, OC / 64, BATCH), 256, QKV_SMEM>>>(qkv_w, qkv_b);
    attn_mma_kernel<<<dim3(HWDIM / 256, NH, BATCH), 256, ATTN_SMEM_BYTES>>>(att_p);
    proj_kernel<<<dim3(HWDIM / 64, CDIM / 64, BATCH), 256>>>(
        proj_w, proj_b, att_p, out, xn_p);
}